// round 10
// baseline (speedup 1.0000x reference)
#include <cuda_runtime.h>
#include <cuda_bf16.h>
#include <cuda_fp16.h>
#include <math.h>

#define NNODE 100000
#define NEDGE 1600000
#define ETOT  (NEDGE + NNODE)
#define HDIM  64
#define GBAT  128
#define SCAN_B 1024
#define SENTINEL (-2147483647 - 1)

// ---------------- scratch (__device__ globals) ------------------------------
__device__ __half2 g_hxh[NNODE * 32];   // h in fp16 (only consumer: agg gather)
__device__ float g_h1 [NNODE * HDIM];   // layer output relu(agg+b)
__device__ float g_s  [NNODE];
__device__ float g_d  [NNODE];
__device__ int   g_cnt[NNODE];          // zeroed each call inside scan_kernel
__device__ int   g_off[NNODE + 1];
__device__ int   g_pos[NNODE];
__device__ int   g_flag[128];           // chained-scan flags
__device__ int   g_srcs[ETOT];
__device__ float g_w1t[HDIM * HDIM];    // tf32 bit patterns of W1/W2
__device__ float g_w2t[HDIM * HDIM];
__device__ float g_x1 [GBAT * 2 * HDIM]; // zeroed each call by out_kernel
__device__ float g_x2 [GBAT * 2 * HDIM];

__device__ __forceinline__ unsigned tf32_of(float f) {
    unsigned r;
    asm("cvt.rna.tf32.f32 %0, %1;" : "=r"(r) : "f"(f));
    return r;
}

// ======== hist: in-degree histogram + flag init + W tf32 pre-convert =========
__global__ void hist_kernel(const int* __restrict__ ei, int E,
                            const float* __restrict__ W1,
                            const float* __restrict__ W2) {
    int t = threadIdx.x;
    int i = blockIdx.x * blockDim.x + t;
    if (blockIdx.x == 0) {
        if (t < 128) g_flag[t] = SENTINEL;
        for (int k = t; k < HDIM * HDIM; k += blockDim.x) {
            g_w1t[k] = __uint_as_float(tf32_of(W1[k]));
            g_w2t[k] = __uint_as_float(tf32_of(W2[k]));
        }
    }
    if (i < E) atomicAdd(&g_cnt[ei[E + i]], 1);
}

// ======== fused scan: offsets + self-loop seed + pos init + cnt reset ========
__global__ void scan_kernel(int n, int etot) {
    int t = threadIdx.x;                 // 1024
    int lane = t & 31, wid = t >> 5;
    int bid = blockIdx.x;
    int i = bid * SCAN_B + t;
    int v = (i < n) ? (g_cnt[i] + 1) : 0;   // +1 self loop

    // warp-shuffle inclusive scan
    int s = v;
    #pragma unroll
    for (int o = 1; o < 32; o <<= 1) {
        int u = __shfl_up_sync(0xffffffffu, s, o);
        if (lane >= o) s += u;
    }
    __shared__ int wsum[32];
    if (lane == 31) wsum[wid] = s;
    __syncthreads();
    if (wid == 0) {
        int ws = wsum[lane];
        #pragma unroll
        for (int o = 1; o < 32; o <<= 1) {
            int u = __shfl_up_sync(0xffffffffu, ws, o);
            if (lane >= o) ws += u;
        }
        wsum[lane] = ws;                 // inclusive over warps
    }
    __syncthreads();
    int incl = s + (wid > 0 ? wsum[wid - 1] : 0);
    int total = wsum[31];

    // cross-block chain (grid = 98 blocks <= #SM, all resident)
    __shared__ int prev_s;
    if (t == 0) {
        int prev = 0;
        if (bid > 0) {
            int f;
            do { f = atomicAdd(&g_flag[bid - 1], 0); } while (f == SENTINEL);
            prev = f;
        }
        atomicExch(&g_flag[bid], prev + total);
        prev_s = prev;
    }
    __syncthreads();
    int off = prev_s + incl - v;         // exclusive global offset
    if (i < n) {
        g_off[i] = off;
        g_srcs[off] = i;                 // self loop first
        g_pos[i] = off + 1;
        g_cnt[i] = 0;                    // ready for next call
    }
    if (i == 0) g_off[n] = etot;
}

// ======== scatter edges into CSR + flag reset for next call ==================
__global__ void scatter_kernel(const int* __restrict__ ei, int E) {
    int t = threadIdx.x;
    int i = blockIdx.x * blockDim.x + t;
    if (blockIdx.x == 0 && t < 128) g_flag[t] = SENTINEL;
    if (i < E) {
        int dst = ei[E + i];
        int slot = atomicAdd(&g_pos[dst], 1);
        g_srcs[slot] = ei[i];
    }
}

// ======== TF32 tensor-core GEMM + attention scalars ==========================
// g_hxh[r,:] = fp16(src[r,:] @ W) ; g_s[r] = h.a_s ; g_d[r] = h.a_d
// 128 threads = 4 warps; block = 64 rows; X and pre-converted W via cp.async.
// which_w: 1 -> g_w1t, 2 -> g_w2t (device symbols referenced in-kernel only)
__global__ __launch_bounds__(128) void gemmsd_kernel(
        const float* __restrict__ X,
        const float* __restrict__ a_s, const float* __restrict__ a_d,
        int n, int use_internal, int which_w) {
    __shared__ float sW[64 * 68];          // tf32 bits, padded stride
    __shared__ float sX[64 * 68];          // fp32 X tile, padded stride
    __shared__ float sas[64], sad[64];
    int t = threadIdx.x;                   // 128
    int warp = t >> 5, lane = t & 31;
    int gid = lane >> 2, tg = lane & 3;

    const float* Xp = use_internal ? g_h1 : X;
    const float* Wt = (which_w == 1) ? g_w1t : g_w2t;
    int rowbase = blockIdx.x * 64;

    {
        unsigned sxb, swb;
        asm("{ .reg .u64 a; cvta.to.shared.u64 a, %1; cvt.u32.u64 %0, a; }"
            : "=r"(sxb) : "l"((void*)sX));
        asm("{ .reg .u64 a; cvta.to.shared.u64 a, %1; cvt.u32.u64 %0, a; }"
            : "=r"(swb) : "l"((void*)sW));
        #pragma unroll
        for (int it = 0; it < 8; it++) {
            int i = it * 128 + t;
            int row = i >> 4, c4 = i & 15;
            // X tile (zero-fill OOB rows)
            int grow = rowbase + row;
            int valid = (grow < n) ? 16 : 0;
            int crow = (grow < n) ? grow : 0;
            const float* srcx = Xp + (size_t)crow * 64 + c4 * 4;
            asm volatile("cp.async.cg.shared.global [%0], [%1], 16, %2;"
                         :: "r"(sxb + row * 272 + c4 * 16), "l"(srcx), "r"(valid));
            // W tile (pre-converted tf32 bits)
            const float* srcw = Wt + row * 64 + c4 * 4;
            asm volatile("cp.async.cg.shared.global [%0], [%1], 16;"
                         :: "r"(swb + row * 272 + c4 * 16), "l"(srcw));
        }
        asm volatile("cp.async.commit_group;");
    }

    if (t < 64) { sas[t] = a_s[t]; sad[t] = a_d[t]; }
    asm volatile("cp.async.wait_group 0;");
    __syncthreads();

    int lr0 = warp * 16 + gid, lr1 = lr0 + 8;   // local rows
    int r0 = rowbase + lr0, r1 = rowbase + lr1;
    bool v0 = r0 < n, v1 = r1 < n;

    float c[8][4];
    #pragma unroll
    for (int nt = 0; nt < 8; nt++)
        c[nt][0] = c[nt][1] = c[nt][2] = c[nt][3] = 0.0f;

    #pragma unroll
    for (int kb = 0; kb < 8; kb++) {
        int k0 = kb * 8 + tg;
        unsigned a0 = tf32_of(sX[lr0 * 68 + k0]);
        unsigned a1 = tf32_of(sX[lr1 * 68 + k0]);
        unsigned a2 = tf32_of(sX[lr0 * 68 + k0 + 4]);
        unsigned a3 = tf32_of(sX[lr1 * 68 + k0 + 4]);
        #pragma unroll
        for (int nt = 0; nt < 8; nt++) {
            unsigned b0 = __float_as_uint(sW[k0       * 68 + nt * 8 + gid]);
            unsigned b1 = __float_as_uint(sW[(k0 + 4) * 68 + nt * 8 + gid]);
            asm volatile(
                "mma.sync.aligned.m16n8k8.row.col.f32.tf32.tf32.f32 "
                "{%0,%1,%2,%3}, {%4,%5,%6,%7}, {%8,%9}, {%0,%1,%2,%3};"
                : "+f"(c[nt][0]), "+f"(c[nt][1]), "+f"(c[nt][2]), "+f"(c[nt][3])
                : "r"(a0), "r"(a1), "r"(a2), "r"(a3), "r"(b0), "r"(b1));
        }
    }

    // epilogue: store h as half2 + fused s/d
    float s0 = 0.f, d0 = 0.f, s1 = 0.f, d1 = 0.f;
    #pragma unroll
    for (int nt = 0; nt < 8; nt++) {
        int cc = nt * 8 + 2 * tg;
        if (v0) g_hxh[r0 * 32 + nt * 4 + tg] = __floats2half2_rn(c[nt][0], c[nt][1]);
        if (v1) g_hxh[r1 * 32 + nt * 4 + tg] = __floats2half2_rn(c[nt][2], c[nt][3]);
        s0 += c[nt][0] * sas[cc] + c[nt][1] * sas[cc + 1];
        d0 += c[nt][0] * sad[cc] + c[nt][1] * sad[cc + 1];
        s1 += c[nt][2] * sas[cc] + c[nt][3] * sas[cc + 1];
        d1 += c[nt][2] * sad[cc] + c[nt][3] * sad[cc + 1];
    }
    #pragma unroll
    for (int o = 1; o < 4; o <<= 1) {
        s0 += __shfl_xor_sync(0xffffffffu, s0, o);
        d0 += __shfl_xor_sync(0xffffffffu, d0, o);
        s1 += __shfl_xor_sync(0xffffffffu, s1, o);
        d1 += __shfl_xor_sync(0xffffffffu, d1, o);
    }
    if (tg == 0) {
        if (v0) { g_s[r0] = s0; g_d[r0] = d0; }
        if (v1) { g_s[r1] = s1; g_d[r1] = d1; }
    }
}

// ======== fused softmax + aggregation: warp per dst node =====================
__global__ void gat_agg_kernel(const float* __restrict__ b, int n) {
    int w = (blockIdx.x * blockDim.x + threadIdx.x) >> 5;
    int lane = threadIdx.x & 31;
    if (w >= n) return;
    int beg = g_off[w], end = g_off[w + 1];
    int deg = end - beg;
    float dd = g_d[w];
    float2 bv = ((const float2*)b)[lane];
    float a0 = 0.f, a1 = 0.f;

    if (deg <= 32) {
        float l = -INFINITY; int ssrc = 0;
        if (lane < deg) {
            ssrc = g_srcs[beg + lane];
            l = g_s[ssrc] + dd;
            l = (l > 0.0f) ? l : 0.2f * l;
        }
        float m = l;
        #pragma unroll
        for (int o = 16; o; o >>= 1)
            m = fmaxf(m, __shfl_xor_sync(0xffffffffu, m, o));
        float wexp = (lane < deg) ? __expf(l - m) : 0.0f;
        float den = wexp;
        #pragma unroll
        for (int o = 16; o; o >>= 1)
            den += __shfl_xor_sync(0xffffffffu, den, o);
        wexp *= (1.0f / den);               // pre-normalized weight

        for (int k = 0; k < deg; k++) {
            float wgt = __shfl_sync(0xffffffffu, wexp, k);
            int   src = __shfl_sync(0xffffffffu, ssrc, k);
            float2 h = __half22float2(g_hxh[src * 32 + lane]);
            a0 += wgt * h.x;
            a1 += wgt * h.y;
        }
    } else {
        float m = -INFINITY;
        for (int e = beg + lane; e < end; e += 32) {
            int src = g_srcs[e];
            float l = g_s[src] + dd;
            l = (l > 0.0f) ? l : 0.2f * l;
            m = fmaxf(m, l);
        }
        #pragma unroll
        for (int o = 16; o; o >>= 1)
            m = fmaxf(m, __shfl_xor_sync(0xffffffffu, m, o));
        float den = 0.f;
        for (int e = beg + lane; e < end; e += 32) {
            int src = g_srcs[e];
            float l = g_s[src] + dd;
            l = (l > 0.0f) ? l : 0.2f * l;
            den += __expf(l - m);
        }
        #pragma unroll
        for (int o = 16; o; o >>= 1)
            den += __shfl_xor_sync(0xffffffffu, den, o);
        float inv = 1.0f / den;
        for (int e = beg; e < end; e++) {
            int src = g_srcs[e];
            float l = g_s[src] + dd;
            l = (l > 0.0f) ? l : 0.2f * l;
            float wgt = __expf(l - m) * inv;
            float2 h = __half22float2(g_hxh[src * 32 + lane]);
            a0 += wgt * h.x;
            a1 += wgt * h.y;
        }
    }
    ((float2*)g_h1)[w * 32 + lane] =
        make_float2(fmaxf(a0 + bv.x, 0.0f), fmaxf(a1 + bv.y, 0.0f));
}

// ================= pooling ===================================================
__device__ __forceinline__ int lower_bound_i(const int* a, int n, int v) {
    int lo = 0, hi = n;
    while (lo < hi) { int mid = (lo + hi) >> 1; if (a[mid] < v) lo = mid + 1; else hi = mid; }
    return lo;
}

#define PSPLIT 8
__global__ void pool_kernel(const int* __restrict__ batch, int n, int which) {
    int g = blockIdx.x;
    int part = blockIdx.y;
    int t = threadIdx.x;          // 256
    int c = t & 63, sub = t >> 6;
    int lo = lower_bound_i(batch, n, g);
    int hi = lower_bound_i(batch, n, g + 1);
    int len = hi - lo;
    int p0 = lo + (int)(((long long)len * part) / PSPLIT);
    int p1 = lo + (int)(((long long)len * (part + 1)) / PSPLIT);
    float mx = 0.0f, sm = 0.0f;   // h1 >= 0 after relu
    for (int i = p0 + sub; i < p1; i += 4) {
        float v = g_h1[i * 64 + c];
        mx = fmaxf(mx, v);
        sm += v;
    }
    __shared__ float smx[256], ssm[256];
    smx[t] = mx; ssm[t] = sm;
    __syncthreads();
    if (sub == 0) {
        #pragma unroll
        for (int k = 1; k < 4; k++) {
            mx = fmaxf(mx, smx[k * 64 + c]);
            sm += ssm[k * 64 + c];
        }
        float* Xout = which ? g_x2 : g_x1;
        atomicMax((int*)&Xout[g * 128 + c], __float_as_int(mx));
        atomicAdd(&Xout[g * 128 + 64 + c], sm);
    }
}

// ================= output MLP: one block per graph ==========================
__global__ void out_kernel(const int* __restrict__ batch, int n,
                           const float* __restrict__ L1W,
                           const float* __restrict__ L1b,
                           const float* __restrict__ L2W,
                           const float* __restrict__ L2b,
                           float* __restrict__ out) {
    int g = blockIdx.x;
    int t = threadIdx.x;          // 64 threads
    __shared__ float zin[128];
    __shared__ float red[2];
    int lo = lower_bound_i(batch, n, g);
    int hi = lower_bound_i(batch, n, g + 1);
    float invc = 1.0f / fmaxf((float)(hi - lo), 1.0f);
    for (int k = t; k < 128; k += 64) {
        float v1 = g_x1[g * 128 + k];
        float v2 = g_x2[g * 128 + k];
        if (k >= 64) { v1 *= invc; v2 *= invc; }
        zin[k] = v1 + v2;
    }
    __syncthreads();
    // reset pool accumulators for the next call
    g_x1[g * 128 + t] = 0.0f; g_x1[g * 128 + 64 + t] = 0.0f;
    g_x2[g * 128 + t] = 0.0f; g_x2[g * 128 + 64 + t] = 0.0f;

    float acc = L1b[t];
    #pragma unroll 8
    for (int k = 0; k < 128; k++)
        acc += zin[k] * L1W[k * 64 + t];
    acc = fmaxf(acc, 0.0f);
    float part = acc * L2W[t];
    #pragma unroll
    for (int o = 16; o; o >>= 1)
        part += __shfl_xor_sync(0xffffffffu, part, o);
    if ((t & 31) == 0) red[t >> 5] = part;
    __syncthreads();
    if (t == 0) out[g] = red[0] + red[1] + L2b[0];
}

// ================= launch ====================================================
extern "C" void kernel_launch(void* const* d_in, const int* in_sizes, int n_in,
                              void* d_out, int out_size) {
    const float* x       = (const float*)d_in[0];
    const int*   ei      = (const int*)  d_in[1];
    const int*   batch   = (const int*)  d_in[2];
    const float* W1      = (const float*)d_in[3];
    const float* a_src1  = (const float*)d_in[4];
    const float* a_dst1  = (const float*)d_in[5];
    const float* b1      = (const float*)d_in[6];
    const float* W2      = (const float*)d_in[7];
    const float* a_src2  = (const float*)d_in[8];
    const float* a_dst2  = (const float*)d_in[9];
    const float* b2      = (const float*)d_in[10];
    const float* lin1_W  = (const float*)d_in[11];
    const float* lin1_b  = (const float*)d_in[12];
    const float* lin2_W  = (const float*)d_in[13];
    const float* lin2_b  = (const float*)d_in[14];
    float* out = (float*)d_out;

    int n    = in_sizes[0] / HDIM;     // 100000
    int E    = in_sizes[1] / 2;        // 1600000
    int etot = E + n;
    int nb   = (n + SCAN_B - 1) / SCAN_B;   // 98 blocks (<= #SM)

    hist_kernel<<<(E + 255) / 256, 256>>>(ei, E, W1, W2);              // 0
    scan_kernel<<<nb, SCAN_B>>>(n, etot);                              // 1
    scatter_kernel<<<(E + 255) / 256, 256>>>(ei, E);                   // 2
    gemmsd_kernel<<<(n + 63) / 64, 128>>>(x, a_src1, a_dst1, n, 0, 1); // 3 <- profiled
    gat_agg_kernel<<<(n * 32 + 255) / 256, 256>>>(b1, n);              // 4
    pool_kernel<<<dim3(GBAT, PSPLIT), 256>>>(batch, n, 0);             // 5
    gemmsd_kernel<<<(n + 63) / 64, 128>>>(nullptr, a_src2, a_dst2, n, 1, 2); // 6
    gat_agg_kernel<<<(n * 32 + 255) / 256, 256>>>(b2, n);              // 7
    pool_kernel<<<dim3(GBAT, PSPLIT), 256>>>(batch, n, 1);             // 8
    out_kernel<<<GBAT, 64>>>(batch, n, lin1_W, lin1_b, lin2_W, lin2_b, out); // 9
}

// round 11
// speedup vs baseline: 1.2002x; 1.2002x over previous
#include <cuda_runtime.h>
#include <cuda_bf16.h>
#include <cuda_fp16.h>
#include <math.h>

#define NNODE 100000
#define NEDGE 1600000
#define ETOT  (NEDGE + NNODE)
#define HDIM  64
#define GBAT  128
#define SCAN_B 1024

// ---------------- scratch (__device__ globals) ------------------------------
__device__ __half2 g_hxh[NNODE * 32];   // h in fp16 (only consumer: agg gather)
__device__ float g_h1 [NNODE * HDIM];   // layer output relu(agg+b)
__device__ float g_s  [NNODE];
__device__ float g_d  [NNODE];
__device__ int   g_cnt[NNODE];          // zeroed each call (scanBC)
__device__ int   g_off[NNODE + 1];
__device__ int   g_pos[NNODE];
__device__ int   g_part[128];           // per-block scan totals
__device__ int   g_srcs[ETOT];
__device__ float g_w1t[HDIM * HDIM];    // tf32 bit patterns of W1/W2
__device__ float g_w2t[HDIM * HDIM];
__device__ float g_x1 [GBAT * 2 * HDIM]; // zeroed each call by out_kernel
__device__ float g_x2 [GBAT * 2 * HDIM];

__device__ __forceinline__ unsigned tf32_of(float f) {
    unsigned r;
    asm("cvt.rna.tf32.f32 %0, %1;" : "=r"(r) : "f"(f));
    return r;
}

// ======== hist: in-degree histogram + W tf32 pre-convert =====================
__global__ void hist_kernel(const int* __restrict__ ei, int E,
                            const float* __restrict__ W1,
                            const float* __restrict__ W2) {
    int t = threadIdx.x;
    int i = blockIdx.x * blockDim.x + t;
    if (blockIdx.x == 0) {
        for (int k = t; k < HDIM * HDIM; k += blockDim.x) {
            g_w1t[k] = __uint_as_float(tf32_of(W1[k]));
            g_w2t[k] = __uint_as_float(tf32_of(W2[k]));
        }
    }
    if (i < E) atomicAdd(&g_cnt[ei[E + i]], 1);
}

// ======== scanA: block-local exclusive scan (warp shuffles) ==================
__global__ void scanA_kernel(int n) {
    int t = threadIdx.x;                 // 1024
    int lane = t & 31, wid = t >> 5;
    int i = blockIdx.x * SCAN_B + t;
    int v = (i < n) ? (g_cnt[i] + 1) : 0;   // +1 self loop

    int s = v;
    #pragma unroll
    for (int o = 1; o < 32; o <<= 1) {
        int u = __shfl_up_sync(0xffffffffu, s, o);
        if (lane >= o) s += u;
    }
    __shared__ int wsum[32];
    if (lane == 31) wsum[wid] = s;
    __syncthreads();
    if (wid == 0) {
        int ws = wsum[lane];
        #pragma unroll
        for (int o = 1; o < 32; o <<= 1) {
            int u = __shfl_up_sync(0xffffffffu, ws, o);
            if (lane >= o) ws += u;
        }
        wsum[lane] = ws;
    }
    __syncthreads();
    int incl = s + (wid > 0 ? wsum[wid - 1] : 0);
    if (i < n) g_off[i] = incl - v;          // block-local exclusive
    if (t == SCAN_B - 1) g_part[blockIdx.x] = incl;
}

// ======== scanBC: add block prefix + seed self-loop + pos init + cnt reset ===
__global__ void scanBC_kernel(int n, int etot) {
    int t = threadIdx.x;                 // 1024
    int lane = t & 31, wid = t >> 5;
    int bid = blockIdx.x;
    // prefix = sum of g_part[0..bid): parallel reduce (<=97 values, no spin)
    __shared__ int wred[32];
    __shared__ int pref_s;
    int v = (t < bid) ? g_part[t] : 0;
    #pragma unroll
    for (int o = 16; o; o >>= 1) v += __shfl_xor_sync(0xffffffffu, v, o);
    if (lane == 0) wred[wid] = v;
    __syncthreads();
    if (wid == 0) {
        int u = wred[lane];
        #pragma unroll
        for (int o = 16; o; o >>= 1) u += __shfl_xor_sync(0xffffffffu, u, o);
        if (lane == 0) pref_s = u;
    }
    __syncthreads();
    int i = bid * SCAN_B + t;
    if (i < n) {
        int o = g_off[i] + pref_s;
        g_off[i] = o;
        g_srcs[o] = i;                   // self loop first
        g_pos[i] = o + 1;
        g_cnt[i] = 0;                    // ready for next call
    }
    if (i == n) g_off[n] = etot;
}

// ======== scatter edges into CSR =============================================
__global__ void scatter_kernel(const int* __restrict__ ei, int E) {
    int i = blockIdx.x * blockDim.x + threadIdx.x;
    if (i < E) {
        int dst = ei[E + i];
        int slot = atomicAdd(&g_pos[dst], 1);
        g_srcs[slot] = ei[i];
    }
}

// ======== TF32 tensor-core GEMM + attention scalars ==========================
// g_hxh[r,:] = fp16(src[r,:] @ W) ; g_s[r] = h.a_s ; g_d[r] = h.a_d
// which_w: 1 -> g_w1t, 2 -> g_w2t (device symbols referenced in-kernel only)
__global__ __launch_bounds__(128) void gemmsd_kernel(
        const float* __restrict__ X,
        const float* __restrict__ a_s, const float* __restrict__ a_d,
        int n, int use_internal, int which_w) {
    __shared__ float sW[64 * 68];          // tf32 bits, padded stride
    __shared__ float sX[64 * 68];          // fp32 X tile, padded stride
    __shared__ float sas[64], sad[64];
    int t = threadIdx.x;                   // 128
    int warp = t >> 5, lane = t & 31;
    int gid = lane >> 2, tg = lane & 3;

    const float* Xp = use_internal ? g_h1 : X;
    const float* Wt = (which_w == 1) ? g_w1t : g_w2t;
    int rowbase = blockIdx.x * 64;

    {
        unsigned sxb, swb;
        asm("{ .reg .u64 a; cvta.to.shared.u64 a, %1; cvt.u32.u64 %0, a; }"
            : "=r"(sxb) : "l"((void*)sX));
        asm("{ .reg .u64 a; cvta.to.shared.u64 a, %1; cvt.u32.u64 %0, a; }"
            : "=r"(swb) : "l"((void*)sW));
        #pragma unroll
        for (int it = 0; it < 8; it++) {
            int i = it * 128 + t;
            int row = i >> 4, c4 = i & 15;
            int grow = rowbase + row;
            int valid = (grow < n) ? 16 : 0;
            int crow = (grow < n) ? grow : 0;
            const float* srcx = Xp + (size_t)crow * 64 + c4 * 4;
            asm volatile("cp.async.cg.shared.global [%0], [%1], 16, %2;"
                         :: "r"(sxb + row * 272 + c4 * 16), "l"(srcx), "r"(valid));
            const float* srcw = Wt + row * 64 + c4 * 4;
            asm volatile("cp.async.cg.shared.global [%0], [%1], 16;"
                         :: "r"(swb + row * 272 + c4 * 16), "l"(srcw));
        }
        asm volatile("cp.async.commit_group;");
    }

    if (t < 64) { sas[t] = a_s[t]; sad[t] = a_d[t]; }
    asm volatile("cp.async.wait_group 0;");
    __syncthreads();

    int lr0 = warp * 16 + gid, lr1 = lr0 + 8;
    int r0 = rowbase + lr0, r1 = rowbase + lr1;
    bool v0 = r0 < n, v1 = r1 < n;

    float c[8][4];
    #pragma unroll
    for (int nt = 0; nt < 8; nt++)
        c[nt][0] = c[nt][1] = c[nt][2] = c[nt][3] = 0.0f;

    #pragma unroll
    for (int kb = 0; kb < 8; kb++) {
        int k0 = kb * 8 + tg;
        unsigned a0 = tf32_of(sX[lr0 * 68 + k0]);
        unsigned a1 = tf32_of(sX[lr1 * 68 + k0]);
        unsigned a2 = tf32_of(sX[lr0 * 68 + k0 + 4]);
        unsigned a3 = tf32_of(sX[lr1 * 68 + k0 + 4]);
        #pragma unroll
        for (int nt = 0; nt < 8; nt++) {
            unsigned b0 = __float_as_uint(sW[k0       * 68 + nt * 8 + gid]);
            unsigned b1 = __float_as_uint(sW[(k0 + 4) * 68 + nt * 8 + gid]);
            asm volatile(
                "mma.sync.aligned.m16n8k8.row.col.f32.tf32.tf32.f32 "
                "{%0,%1,%2,%3}, {%4,%5,%6,%7}, {%8,%9}, {%0,%1,%2,%3};"
                : "+f"(c[nt][0]), "+f"(c[nt][1]), "+f"(c[nt][2]), "+f"(c[nt][3])
                : "r"(a0), "r"(a1), "r"(a2), "r"(a3), "r"(b0), "r"(b1));
        }
    }

    float s0 = 0.f, d0 = 0.f, s1 = 0.f, d1 = 0.f;
    #pragma unroll
    for (int nt = 0; nt < 8; nt++) {
        int cc = nt * 8 + 2 * tg;
        if (v0) g_hxh[r0 * 32 + nt * 4 + tg] = __floats2half2_rn(c[nt][0], c[nt][1]);
        if (v1) g_hxh[r1 * 32 + nt * 4 + tg] = __floats2half2_rn(c[nt][2], c[nt][3]);
        s0 += c[nt][0] * sas[cc] + c[nt][1] * sas[cc + 1];
        d0 += c[nt][0] * sad[cc] + c[nt][1] * sad[cc + 1];
        s1 += c[nt][2] * sas[cc] + c[nt][3] * sas[cc + 1];
        d1 += c[nt][2] * sad[cc] + c[nt][3] * sad[cc + 1];
    }
    #pragma unroll
    for (int o = 1; o < 4; o <<= 1) {
        s0 += __shfl_xor_sync(0xffffffffu, s0, o);
        d0 += __shfl_xor_sync(0xffffffffu, d0, o);
        s1 += __shfl_xor_sync(0xffffffffu, s1, o);
        d1 += __shfl_xor_sync(0xffffffffu, d1, o);
    }
    if (tg == 0) {
        if (v0) { g_s[r0] = s0; g_d[r0] = d0; }
        if (v1) { g_s[r1] = s1; g_d[r1] = d1; }
    }
}

// ======== fused softmax + aggregation: warp per dst node =====================
__global__ void gat_agg_kernel(const float* __restrict__ b, int n) {
    int w = (blockIdx.x * blockDim.x + threadIdx.x) >> 5;
    int lane = threadIdx.x & 31;
    if (w >= n) return;
    int beg = g_off[w], end = g_off[w + 1];
    int deg = end - beg;
    float dd = g_d[w];
    float2 bv = ((const float2*)b)[lane];
    float a0 = 0.f, a1 = 0.f;

    if (deg <= 32) {
        float l = -INFINITY; int ssrc = 0;
        if (lane < deg) {
            ssrc = g_srcs[beg + lane];
            l = g_s[ssrc] + dd;
            l = (l > 0.0f) ? l : 0.2f * l;
        }
        float m = l;
        #pragma unroll
        for (int o = 16; o; o >>= 1)
            m = fmaxf(m, __shfl_xor_sync(0xffffffffu, m, o));
        float wexp = (lane < deg) ? __expf(l - m) : 0.0f;
        float den = wexp;
        #pragma unroll
        for (int o = 16; o; o >>= 1)
            den += __shfl_xor_sync(0xffffffffu, den, o);
        wexp *= (1.0f / den);               // pre-normalized weight

        for (int k = 0; k < deg; k++) {
            float wgt = __shfl_sync(0xffffffffu, wexp, k);
            int   src = __shfl_sync(0xffffffffu, ssrc, k);
            float2 h = __half22float2(g_hxh[src * 32 + lane]);
            a0 += wgt * h.x;
            a1 += wgt * h.y;
        }
    } else {
        float m = -INFINITY;
        for (int e = beg + lane; e < end; e += 32) {
            int src = g_srcs[e];
            float l = g_s[src] + dd;
            l = (l > 0.0f) ? l : 0.2f * l;
            m = fmaxf(m, l);
        }
        #pragma unroll
        for (int o = 16; o; o >>= 1)
            m = fmaxf(m, __shfl_xor_sync(0xffffffffu, m, o));
        float den = 0.f;
        for (int e = beg + lane; e < end; e += 32) {
            int src = g_srcs[e];
            float l = g_s[src] + dd;
            l = (l > 0.0f) ? l : 0.2f * l;
            den += __expf(l - m);
        }
        #pragma unroll
        for (int o = 16; o; o >>= 1)
            den += __shfl_xor_sync(0xffffffffu, den, o);
        float inv = 1.0f / den;
        for (int e = beg; e < end; e++) {
            int src = g_srcs[e];
            float l = g_s[src] + dd;
            l = (l > 0.0f) ? l : 0.2f * l;
            float wgt = __expf(l - m) * inv;
            float2 h = __half22float2(g_hxh[src * 32 + lane]);
            a0 += wgt * h.x;
            a1 += wgt * h.y;
        }
    }
    ((float2*)g_h1)[w * 32 + lane] =
        make_float2(fmaxf(a0 + bv.x, 0.0f), fmaxf(a1 + bv.y, 0.0f));
}

// ================= pooling ===================================================
__device__ __forceinline__ int lower_bound_i(const int* a, int n, int v) {
    int lo = 0, hi = n;
    while (lo < hi) { int mid = (lo + hi) >> 1; if (a[mid] < v) lo = mid + 1; else hi = mid; }
    return lo;
}

#define PSPLIT 8
__global__ void pool_kernel(const int* __restrict__ batch, int n, int which) {
    int g = blockIdx.x;
    int part = blockIdx.y;
    int t = threadIdx.x;          // 256
    int c = t & 63, sub = t >> 6;
    int lo = lower_bound_i(batch, n, g);
    int hi = lower_bound_i(batch, n, g + 1);
    int len = hi - lo;
    int p0 = lo + (int)(((long long)len * part) / PSPLIT);
    int p1 = lo + (int)(((long long)len * (part + 1)) / PSPLIT);
    float mx = 0.0f, sm = 0.0f;   // h1 >= 0 after relu
    for (int i = p0 + sub; i < p1; i += 4) {
        float v = g_h1[i * 64 + c];
        mx = fmaxf(mx, v);
        sm += v;
    }
    __shared__ float smx[256], ssm[256];
    smx[t] = mx; ssm[t] = sm;
    __syncthreads();
    if (sub == 0) {
        #pragma unroll
        for (int k = 1; k < 4; k++) {
            mx = fmaxf(mx, smx[k * 64 + c]);
            sm += ssm[k * 64 + c];
        }
        float* Xout = which ? g_x2 : g_x1;
        atomicMax((int*)&Xout[g * 128 + c], __float_as_int(mx));
        atomicAdd(&Xout[g * 128 + 64 + c], sm);
    }
}

// ================= output MLP: one block per graph ==========================
__global__ void out_kernel(const int* __restrict__ batch, int n,
                           const float* __restrict__ L1W,
                           const float* __restrict__ L1b,
                           const float* __restrict__ L2W,
                           const float* __restrict__ L2b,
                           float* __restrict__ out) {
    int g = blockIdx.x;
    int t = threadIdx.x;          // 64 threads
    __shared__ float zin[128];
    __shared__ float red[2];
    int lo = lower_bound_i(batch, n, g);
    int hi = lower_bound_i(batch, n, g + 1);
    float invc = 1.0f / fmaxf((float)(hi - lo), 1.0f);
    for (int k = t; k < 128; k += 64) {
        float v1 = g_x1[g * 128 + k];
        float v2 = g_x2[g * 128 + k];
        if (k >= 64) { v1 *= invc; v2 *= invc; }
        zin[k] = v1 + v2;
    }
    __syncthreads();
    // reset pool accumulators for the next call
    g_x1[g * 128 + t] = 0.0f; g_x1[g * 128 + 64 + t] = 0.0f;
    g_x2[g * 128 + t] = 0.0f; g_x2[g * 128 + 64 + t] = 0.0f;

    float acc = L1b[t];
    #pragma unroll 8
    for (int k = 0; k < 128; k++)
        acc += zin[k] * L1W[k * 64 + t];
    acc = fmaxf(acc, 0.0f);
    float part = acc * L2W[t];
    #pragma unroll
    for (int o = 16; o; o >>= 1)
        part += __shfl_xor_sync(0xffffffffu, part, o);
    if ((t & 31) == 0) red[t >> 5] = part;
    __syncthreads();
    if (t == 0) out[g] = red[0] + red[1] + L2b[0];
}

// ================= launch ====================================================
extern "C" void kernel_launch(void* const* d_in, const int* in_sizes, int n_in,
                              void* d_out, int out_size) {
    const float* x       = (const float*)d_in[0];
    const int*   ei      = (const int*)  d_in[1];
    const int*   batch   = (const int*)  d_in[2];
    const float* W1      = (const float*)d_in[3];
    const float* a_src1  = (const float*)d_in[4];
    const float* a_dst1  = (const float*)d_in[5];
    const float* b1      = (const float*)d_in[6];
    const float* W2      = (const float*)d_in[7];
    const float* a_src2  = (const float*)d_in[8];
    const float* a_dst2  = (const float*)d_in[9];
    const float* b2      = (const float*)d_in[10];
    const float* lin1_W  = (const float*)d_in[11];
    const float* lin1_b  = (const float*)d_in[12];
    const float* lin2_W  = (const float*)d_in[13];
    const float* lin2_b  = (const float*)d_in[14];
    float* out = (float*)d_out;

    int n    = in_sizes[0] / HDIM;     // 100000
    int E    = in_sizes[1] / 2;        // 1600000
    int etot = E + n;
    int nb   = (n + SCAN_B - 1) / SCAN_B;   // 98 blocks

    hist_kernel<<<(E + 255) / 256, 256>>>(ei, E, W1, W2);              // 0
    scanA_kernel<<<nb, SCAN_B>>>(n);                                   // 1
    scanBC_kernel<<<nb, SCAN_B>>>(n, etot);                            // 2
    gemmsd_kernel<<<(n + 63) / 64, 128>>>(x, a_src1, a_dst1, n, 0, 1); // 3 <- profiled
    scatter_kernel<<<(E + 255) / 256, 256>>>(ei, E);                   // 4
    gat_agg_kernel<<<(n * 32 + 255) / 256, 256>>>(b1, n);              // 5
    pool_kernel<<<dim3(GBAT, PSPLIT), 256>>>(batch, n, 0);             // 6
    gemmsd_kernel<<<(n + 63) / 64, 128>>>(nullptr, a_src2, a_dst2, n, 1, 2); // 7
    gat_agg_kernel<<<(n * 32 + 255) / 256, 256>>>(b2, n);              // 8
    pool_kernel<<<dim3(GBAT, PSPLIT), 256>>>(batch, n, 1);             // 9
    out_kernel<<<GBAT, 64>>>(batch, n, lin1_W, lin1_b, lin2_W, lin2_b, out); // 10
}